// round 13
// baseline (speedup 1.0000x reference)
#include <cuda_runtime.h>
#include <cuda_bf16.h>

#define B_ 4
#define H_ 16
#define NQ 256
#define D_ 16

typedef unsigned long long u64;

#define ABSM 0x7FFFFFFF7FFFFFFFULL

// ---- packed f32x2 helpers (sm_100a) ---------------------------------------
__device__ __forceinline__ u64 pk(float a, float b) {
    u64 r; asm("mov.b64 %0, {%1,%2};" : "=l"(r) : "f"(a), "f"(b)); return r;
}
__device__ __forceinline__ void upk(u64 v, float& a, float& b) {
    asm("mov.b64 {%0,%1}, %2;" : "=f"(a), "=f"(b) : "l"(v));
}
__device__ __forceinline__ u64 fma2_(u64 a, u64 b, u64 c) {
    u64 r; asm("fma.rn.f32x2 %0, %1, %2, %3;" : "=l"(r) : "l"(a), "l"(b), "l"(c));
    return r;
}
__device__ __forceinline__ u64 add2_(u64 a, u64 b) {
    u64 r; asm("add.rn.f32x2 %0, %1, %2;" : "=l"(r) : "l"(a), "l"(b));
    return r;
}
__device__ __forceinline__ u64 mul2_(u64 a, u64 b) {
    u64 r; asm("mul.rn.f32x2 %0, %1, %2;" : "=l"(r) : "l"(a), "l"(b));
    return r;
}

// Scratch for projected Q/K/V in [b][h][n][d] layout.
__device__ float g_Q[B_ * H_ * NQ * D_];
__device__ float g_K[B_ * H_ * NQ * D_];
__device__ float g_V[B_ * H_ * NQ * D_];

// ---------------------------------------------------------------------------
// Kernel A: QKV projections.  out[m, hd] = sum_e A[m, e] * W[hd, e]
// Tile 32(m) x 64(n), 128 threads, 4x4 micro-tile, K-step 16, double-buffered.
// A is staged PRE-DUPLICATED as (a,a) u64 pairs, so the inner loop needs no
// duplication MOVs: 3 LDS.128 + 8 fma2 per k-iteration (was 2 LDS + 4 pk + 8).
// ---------------------------------------------------------------------------
__global__ __launch_bounds__(128) void qkv_kernel(
    const float* __restrict__ row_emb, const float* __restrict__ col_emb,
    const float* __restrict__ Wq, const float* __restrict__ Wk,
    const float* __restrict__ Wv)
{
    __shared__ __align__(16) u64   As[2][16][36];   // [stage][k][m] dup pairs
    __shared__ __align__(16) float Ws[2][16][68];   // [stage][k][n], padded

    const float* A; const float* W; float* O;
    int z = blockIdx.z;
    if (z == 0)      { A = row_emb; W = Wq; O = g_Q; }
    else if (z == 1) { A = col_emb; W = Wk; O = g_K; }
    else             { A = col_emb; W = Wv; O = g_V; }

    int m0 = blockIdx.y * 32;
    int n0 = blockIdx.x * 64;
    int t  = threadIdx.x;
    int tx = t & 15, ty = t >> 4;      // compute map: 16 x 8 threads
    int lm = t >> 2, lk = (t & 3) * 4; // load map: 32 rows x 16 k

    const float* Ap  = &A[(m0 + lm) * 256 + lk];
    const float* Wp0 = &W[(n0 + lm) * 256 + lk];
    const float* Wp1 = &W[(n0 + 32 + lm) * 256 + lk];

    u64 accp[4][2];
    #pragma unroll
    for (int i = 0; i < 4; i++) { accp[i][0] = 0ull; accp[i][1] = 0ull; }

    // Prologue: fill stage 0.
    {
        float4 av = *(const float4*)Ap;
        float4 w0 = *(const float4*)Wp0;
        float4 w1 = *(const float4*)Wp1;
        As[0][lk + 0][lm] = pk(av.x, av.x);
        As[0][lk + 1][lm] = pk(av.y, av.y);
        As[0][lk + 2][lm] = pk(av.z, av.z);
        As[0][lk + 3][lm] = pk(av.w, av.w);
        Ws[0][lk + 0][lm] = w0.x; Ws[0][lk + 1][lm] = w0.y;
        Ws[0][lk + 2][lm] = w0.z; Ws[0][lk + 3][lm] = w0.w;
        Ws[0][lk + 0][32 + lm] = w1.x; Ws[0][lk + 1][32 + lm] = w1.y;
        Ws[0][lk + 2][32 + lm] = w1.z; Ws[0][lk + 3][32 + lm] = w1.w;
    }
    __syncthreads();

    for (int k0 = 0; k0 < 256; k0 += 16) {
        int cur = (k0 >> 4) & 1, nxt = cur ^ 1;
        float4 av, w0, w1;
        bool more = (k0 + 16) < 256;
        if (more) {
            av = *(const float4*)(Ap  + k0 + 16);
            w0 = *(const float4*)(Wp0 + k0 + 16);
            w1 = *(const float4*)(Wp1 + k0 + 16);
        }
        #pragma unroll
        for (int k = 0; k < 16; k++) {
            ulonglong2 aA = *(const ulonglong2*)&As[cur][k][ty * 4];      // (a0,a0),(a1,a1)
            ulonglong2 aB = *(const ulonglong2*)&As[cur][k][ty * 4 + 2];  // (a2,a2),(a3,a3)
            ulonglong2 bb = *(const ulonglong2*)&Ws[cur][k][tx * 4];      // (b0,b1),(b2,b3)
            accp[0][0] = fma2_(aA.x, bb.x, accp[0][0]);
            accp[0][1] = fma2_(aA.x, bb.y, accp[0][1]);
            accp[1][0] = fma2_(aA.y, bb.x, accp[1][0]);
            accp[1][1] = fma2_(aA.y, bb.y, accp[1][1]);
            accp[2][0] = fma2_(aB.x, bb.x, accp[2][0]);
            accp[2][1] = fma2_(aB.x, bb.y, accp[2][1]);
            accp[3][0] = fma2_(aB.y, bb.x, accp[3][0]);
            accp[3][1] = fma2_(aB.y, bb.y, accp[3][1]);
        }
        if (more) {
            As[nxt][lk + 0][lm] = pk(av.x, av.x);
            As[nxt][lk + 1][lm] = pk(av.y, av.y);
            As[nxt][lk + 2][lm] = pk(av.z, av.z);
            As[nxt][lk + 3][lm] = pk(av.w, av.w);
            Ws[nxt][lk + 0][lm] = w0.x; Ws[nxt][lk + 1][lm] = w0.y;
            Ws[nxt][lk + 2][lm] = w0.z; Ws[nxt][lk + 3][lm] = w0.w;
            Ws[nxt][lk + 0][32 + lm] = w1.x; Ws[nxt][lk + 1][32 + lm] = w1.y;
            Ws[nxt][lk + 2][32 + lm] = w1.z; Ws[nxt][lk + 3][32 + lm] = w1.w;
            __syncthreads();
        }
    }

    int bb = m0 >> 8;
    int hh = (n0 >> 4) + (tx >> 2);
    int dd = (tx & 3) * 4;
    #pragma unroll
    for (int i = 0; i < 4; i++) {
        int r = (m0 & 255) + ty * 4 + i;
        float4 o;
        upk(accp[i][0], o.x, o.y);
        upk(accp[i][1], o.z, o.w);
        *(float4*)&O[((bb * H_ + hh) * NQ + r) * D_ + dd] = o;
    }
}

// ---------------------------------------------------------------------------
// Reduce-scatter over 32 lanes: input acc[8] packed u64 = 16 floats (d pairs).
// Returns full 32-lane sum for d = f(lane); every xor-1 lane pair agrees.
// ---------------------------------------------------------------------------
__device__ __forceinline__ float reduce16(const u64 acc[8], int lane, int& dOut)
{
    bool k16 = (lane & 16) == 0;
    u64 h[4];
    #pragma unroll
    for (int j = 0; j < 4; j++) {
        u64 send = k16 ? acc[4 + j] : acc[j];
        u64 recv = __shfl_xor_sync(0xffffffffu, send, 16);
        u64 mine = k16 ? acc[j] : acc[4 + j];
        h[j] = add2_(mine, recv);
    }
    bool k8 = (lane & 8) == 0;
    u64 g[2];
    #pragma unroll
    for (int j = 0; j < 2; j++) {
        u64 send = k8 ? h[2 + j] : h[j];
        u64 recv = __shfl_xor_sync(0xffffffffu, send, 8);
        u64 mine = k8 ? h[j] : h[2 + j];
        g[j] = add2_(mine, recv);
    }
    bool k4 = (lane & 4) == 0;
    {
        u64 send = k4 ? g[1] : g[0];
        u64 recv = __shfl_xor_sync(0xffffffffu, send, 4);
        u64 mine = k4 ? g[0] : g[1];
        g[0] = add2_(mine, recv);
    }
    float lo, hi; upk(g[0], lo, hi);
    bool k2 = (lane & 2) == 0;
    float send = k2 ? hi : lo;
    float recv = __shfl_xor_sync(0xffffffffu, send, 2);
    float s = (k2 ? lo : hi) + recv;
    s += __shfl_xor_sync(0xffffffffu, s, 1);
    dOut = ((lane & 16) >> 1) | ((lane & 8) >> 1) | ((lane & 4) >> 1) | ((lane & 2) >> 1);
    return s;
}

// ---------------------------------------------------------------------------
// Kernel B: fused scores + mixing-MLP + softmax + AV.  (R10 configuration —
// best measured.)  One warp per TWO rows.  MLP identity:
//   sum_m w2*relu(t_m) = A*dot + B*cost + [C] + sum_m (0.5*w2_m)*|t_m|
// with A = sum 0.5*w2*w1a, B = sum 0.5*w2*w1b; C and mix2_bias are
// softmax-invariant (dropped).  1/sqrt(D) folded into w1a.
// ---------------------------------------------------------------------------
__global__ __launch_bounds__(256, 3) void attn_kernel(
    const float* __restrict__ cost_mat,
    const float* __restrict__ mix1_w,   // [16][2][32]
    const float* __restrict__ mix1_b,   // [16][32]
    const float* __restrict__ mix2_w,   // [16][32][1]
    float* __restrict__ out)            // [B][R][H*D]
{
    __shared__ __align__(16) float Ks[256][20];
    __shared__ __align__(16) float Vs[256][20];
    __shared__ u64   mlpp[32][4];       // (wx pair, wy pair, b1 pair, 0.5*w2 pair)
    __shared__ u64   ABs[2];            // packed (A,A), (B,B)

    int b = blockIdx.z, h = blockIdx.y, rt = blockIdx.x;
    int bh = b * H_ + h;
    int t = threadIdx.x;
    int lane = t & 31, w = t >> 5;
    int r0 = rt * 16 + w * 2;           // this warp handles rows r0, r0+1

    // ---- cooperative K/V tile staging ----
    {
        const float* Kg = g_K + bh * NQ * D_;
        const float* Vg = g_V + bh * NQ * D_;
        #pragma unroll
        for (int j = 0; j < 4; j++) {
            *(float4*)&Ks[t][j * 4] = *(const float4*)&Kg[t * D_ + j * 4];
            *(float4*)&Vs[t][j * 4] = *(const float4*)&Vg[t * D_ + j * 4];
        }
    }
    if (t < 32) {
        float wxv = mix1_w[h * 64 + t] * 0.25f;   // fold 1/sqrt(D)
        float wyv = mix1_w[h * 64 + 32 + t];
        float bzv = mix1_b[h * 32 + t];
        float hwv = mix2_w[h * 32 + t] * 0.5f;    // fold 0.5 of abs-relu identity
        mlpp[t][0] = pk(wxv, wxv);
        mlpp[t][1] = pk(wyv, wyv);
        mlpp[t][2] = pk(bzv, bzv);
        mlpp[t][3] = pk(hwv, hwv);
        float a  = hwv * wxv;
        float bb = hwv * wyv;
        #pragma unroll
        for (int o = 16; o; o >>= 1) {
            a  += __shfl_xor_sync(0xffffffffu, a, o);
            bb += __shfl_xor_sync(0xffffffffu, bb, o);
        }
        if (t == 0) { ABs[0] = pk(a, a); ABs[1] = pk(bb, bb); }
    }
    __syncthreads();

    // ---- Phase 1: raw dot scores (scale folded into wx) ----
    float q0[16], q1[16];
    {
        const float* Qg = g_Q + (bh * NQ + r0) * D_;
        #pragma unroll
        for (int j = 0; j < 4; j++) {
            float4 a = *(const float4*)&Qg[j * 4];
            float4 c = *(const float4*)&Qg[16 + j * 4];
            q0[j*4+0] = a.x; q0[j*4+1] = a.y; q0[j*4+2] = a.z; q0[j*4+3] = a.w;
            q1[j*4+0] = c.x; q1[j*4+1] = c.y; q1[j*4+2] = c.z; q1[j*4+3] = c.w;
        }
    }
    u64 dp0[4], dp1[4];
    #pragma unroll
    for (int p = 0; p < 4; p++) {
        int ca = (2 * p) * 32 + lane;
        int cb = ca + 32;
        float sa0 = 0.f, sa1 = 0.f, sb0 = 0.f, sb1 = 0.f;
        #pragma unroll
        for (int j = 0; j < 4; j++) {
            float4 ka = *(const float4*)&Ks[ca][j * 4];
            float4 kb = *(const float4*)&Ks[cb][j * 4];
            sa0 = fmaf(q0[j*4+0], ka.x, sa0); sa0 = fmaf(q0[j*4+1], ka.y, sa0);
            sa0 = fmaf(q0[j*4+2], ka.z, sa0); sa0 = fmaf(q0[j*4+3], ka.w, sa0);
            sa1 = fmaf(q1[j*4+0], ka.x, sa1); sa1 = fmaf(q1[j*4+1], ka.y, sa1);
            sa1 = fmaf(q1[j*4+2], ka.z, sa1); sa1 = fmaf(q1[j*4+3], ka.w, sa1);
            sb0 = fmaf(q0[j*4+0], kb.x, sb0); sb0 = fmaf(q0[j*4+1], kb.y, sb0);
            sb0 = fmaf(q0[j*4+2], kb.z, sb0); sb0 = fmaf(q0[j*4+3], kb.w, sb0);
            sb1 = fmaf(q1[j*4+0], kb.x, sb1); sb1 = fmaf(q1[j*4+1], kb.y, sb1);
            sb1 = fmaf(q1[j*4+2], kb.z, sb1); sb1 = fmaf(q1[j*4+3], kb.w, sb1);
        }
        dp0[p] = pk(sa0, sb0);
        dp1[p] = pk(sa1, sb1);
    }

    // ---- cost loads (after phase 1 so q regs can retire first) ----
    const float* cr0 = cost_mat + (b * NQ + r0) * NQ;
    const float* cr1 = cr0 + NQ;
    u64 cp0[4], cp1[4];
    #pragma unroll
    for (int p = 0; p < 4; p++) {
        int ca = (2 * p) * 32 + lane;
        cp0[p] = pk(__ldg(cr0 + ca), __ldg(cr0 + ca + 32));
        cp1[p] = pk(__ldg(cr1 + ca), __ldg(cr1 + ca + 32));
    }

    // ---- Phase 2: mixing MLP (abs half only; linear half analytic) ----
    u64 A2 = ABs[0], B2 = ABs[1];
    u64 s0[4], s1[4];
    #pragma unroll
    for (int p = 0; p < 4; p++) {
        s0[p] = fma2_(B2, cp0[p], mul2_(A2, dp0[p]));
        s1[p] = fma2_(B2, cp1[p], mul2_(A2, dp1[p]));
    }
    #pragma unroll 4
    for (int m = 0; m < 32; m++) {
        ulonglong2 w01 = *(const ulonglong2*)&mlpp[m][0];
        ulonglong2 w23 = *(const ulonglong2*)&mlpp[m][2];
        u64 wxx = w01.x, wyy = w01.y, wzz = w23.x, hww = w23.y;
        #pragma unroll
        for (int p = 0; p < 4; p++) {
            u64 t0 = fma2_(wxx, dp0[p], fma2_(wyy, cp0[p], wzz));
            s0[p] = fma2_(hww, t0 & ABSM, s0[p]);
            u64 t1 = fma2_(wxx, dp1[p], fma2_(wyy, cp1[p], wzz));
            s1[p] = fma2_(hww, t1 & ABSM, s1[p]);
        }
    }

    // ---- Phase 3: softmax per row ----
    float sc0[8], sc1[8];
    #pragma unroll
    for (int p = 0; p < 4; p++) {
        upk(s0[p], sc0[2 * p], sc0[2 * p + 1]);
        upk(s1[p], sc1[2 * p], sc1[2 * p + 1]);
    }
    float mx0 = sc0[0], mx1 = sc1[0];
    #pragma unroll
    for (int i = 1; i < 8; i++) { mx0 = fmaxf(mx0, sc0[i]); mx1 = fmaxf(mx1, sc1[i]); }
    #pragma unroll
    for (int o = 16; o; o >>= 1) {
        mx0 = fmaxf(mx0, __shfl_xor_sync(0xffffffffu, mx0, o));
        mx1 = fmaxf(mx1, __shfl_xor_sync(0xffffffffu, mx1, o));
    }
    float sum0 = 0.f, sum1 = 0.f;
    #pragma unroll
    for (int i = 0; i < 8; i++) {
        sc0[i] = __expf(sc0[i] - mx0); sum0 += sc0[i];
        sc1[i] = __expf(sc1[i] - mx1); sum1 += sc1[i];
    }
    #pragma unroll
    for (int o = 16; o; o >>= 1) {
        sum0 += __shfl_xor_sync(0xffffffffu, sum0, o);
        sum1 += __shfl_xor_sync(0xffffffffu, sum1, o);
    }
    float inv0 = 1.f / sum0, inv1 = 1.f / sum1;

    // ---- Phase 4: AV accumulation (V pairs free via ulonglong2) ----
    u64 acc0[8], acc1[8];
    #pragma unroll
    for (int j = 0; j < 8; j++) { acc0[j] = 0ull; acc1[j] = 0ull; }
    #pragma unroll
    for (int i = 0; i < 8; i++) {
        int c = i * 32 + lane;
        u64 w0 = pk(sc0[i], sc0[i]);
        u64 w1 = pk(sc1[i], sc1[i]);
        #pragma unroll
        for (int j = 0; j < 4; j++) {
            ulonglong2 vv = *(const ulonglong2*)&Vs[c][j * 4];
            acc0[2 * j]     = fma2_(w0, vv.x, acc0[2 * j]);
            acc0[2 * j + 1] = fma2_(w0, vv.y, acc0[2 * j + 1]);
            acc1[2 * j]     = fma2_(w1, vv.x, acc1[2 * j]);
            acc1[2 * j + 1] = fma2_(w1, vv.y, acc1[2 * j + 1]);
        }
    }

    // ---- Phase 5: reduce-scatter epilogue ----
    int d0;
    float res0 = reduce16(acc0, lane, d0);
    int d1;
    float res1 = reduce16(acc1, lane, d1);
    if ((lane & 1) == 0) {
        out[(b * NQ + r0)     * (H_ * D_) + h * D_ + d0] = res0 * inv0;
        out[(b * NQ + r0 + 1) * (H_ * D_) + h * D_ + d1] = res1 * inv1;
    }
}

extern "C" void kernel_launch(void* const* d_in, const int* in_sizes, int n_in,
                              void* d_out, int out_size)
{
    const float* row_emb  = (const float*)d_in[0];
    const float* col_emb  = (const float*)d_in[1];
    const float* cost_mat = (const float*)d_in[2];
    const float* Wq       = (const float*)d_in[3];
    const float* Wk       = (const float*)d_in[4];
    const float* Wv       = (const float*)d_in[5];
    const float* m1w      = (const float*)d_in[6];
    const float* m1b      = (const float*)d_in[7];
    const float* m2w      = (const float*)d_in[8];
    // d_in[9] = mix2_bias: softmax-invariant, intentionally unused.
    float* out = (float*)d_out;

    dim3 gA(4, 32, 3);   // n-tiles x m-tiles x {Q,K,V} = 384 blocks
    qkv_kernel<<<gA, 128>>>(row_emb, col_emb, Wq, Wk, Wv);

    dim3 gB(16, 16, 4);  // 16-row tiles x heads x batch = 1024 blocks
    attn_kernel<<<gB, 256>>>(cost_mat, m1w, m1b, m2w, out);
}

// round 15
// speedup vs baseline: 1.0714x; 1.0714x over previous
#include <cuda_runtime.h>
#include <cuda_bf16.h>

#define B_ 4
#define H_ 16
#define NQ 256
#define D_ 16

typedef unsigned long long u64;

#define ABSM 0x7FFFFFFF7FFFFFFFULL

// ---- packed f32x2 helpers (sm_100a) ---------------------------------------
__device__ __forceinline__ u64 pk(float a, float b) {
    u64 r; asm("mov.b64 %0, {%1,%2};" : "=l"(r) : "f"(a), "f"(b)); return r;
}
__device__ __forceinline__ void upk(u64 v, float& a, float& b) {
    asm("mov.b64 {%0,%1}, %2;" : "=f"(a), "=f"(b) : "l"(v));
}
__device__ __forceinline__ u64 fma2_(u64 a, u64 b, u64 c) {
    u64 r; asm("fma.rn.f32x2 %0, %1, %2, %3;" : "=l"(r) : "l"(a), "l"(b), "l"(c));
    return r;
}
__device__ __forceinline__ u64 add2_(u64 a, u64 b) {
    u64 r; asm("add.rn.f32x2 %0, %1, %2;" : "=l"(r) : "l"(a), "l"(b));
    return r;
}
__device__ __forceinline__ u64 mul2_(u64 a, u64 b) {
    u64 r; asm("mul.rn.f32x2 %0, %1, %2;" : "=l"(r) : "l"(a), "l"(b));
    return r;
}

// Scratch for projected Q/K/V in [b][h][n][d] layout.
__device__ float g_Q[B_ * H_ * NQ * D_];
__device__ float g_K[B_ * H_ * NQ * D_];
__device__ float g_V[B_ * H_ * NQ * D_];

// ---------------------------------------------------------------------------
// Kernel A: QKV projections (R10 configuration — best measured).
// Tile 32(m) x 64(n), 128 threads, 4x4 micro-tile, K-step 16, double-buffered
// smem, packed-f32x2 inner with B pairs free via ulonglong2.
// ---------------------------------------------------------------------------
__global__ __launch_bounds__(128) void qkv_kernel(
    const float* __restrict__ row_emb, const float* __restrict__ col_emb,
    const float* __restrict__ Wq, const float* __restrict__ Wk,
    const float* __restrict__ Wv)
{
    __shared__ __align__(16) float As[2][16][36];   // [stage][k][m], padded
    __shared__ __align__(16) float Ws[2][16][68];   // [stage][k][n], padded

    const float* A; const float* W; float* O;
    int z = blockIdx.z;
    if (z == 0)      { A = row_emb; W = Wq; O = g_Q; }
    else if (z == 1) { A = col_emb; W = Wk; O = g_K; }
    else             { A = col_emb; W = Wv; O = g_V; }

    int m0 = blockIdx.y * 32;
    int n0 = blockIdx.x * 64;
    int t  = threadIdx.x;
    int tx = t & 15, ty = t >> 4;      // compute map: 16 x 8 threads
    int lm = t >> 2, lk = (t & 3) * 4; // load map: 32 rows x 16 k

    const float* Ap  = &A[(m0 + lm) * 256 + lk];
    const float* Wp0 = &W[(n0 + lm) * 256 + lk];
    const float* Wp1 = &W[(n0 + 32 + lm) * 256 + lk];

    u64 accp[4][2];
    #pragma unroll
    for (int i = 0; i < 4; i++) { accp[i][0] = 0ull; accp[i][1] = 0ull; }

    // Prologue: fill stage 0.
    {
        float4 av = *(const float4*)Ap;
        float4 w0 = *(const float4*)Wp0;
        float4 w1 = *(const float4*)Wp1;
        As[0][lk + 0][lm] = av.x; As[0][lk + 1][lm] = av.y;
        As[0][lk + 2][lm] = av.z; As[0][lk + 3][lm] = av.w;
        Ws[0][lk + 0][lm] = w0.x; Ws[0][lk + 1][lm] = w0.y;
        Ws[0][lk + 2][lm] = w0.z; Ws[0][lk + 3][lm] = w0.w;
        Ws[0][lk + 0][32 + lm] = w1.x; Ws[0][lk + 1][32 + lm] = w1.y;
        Ws[0][lk + 2][32 + lm] = w1.z; Ws[0][lk + 3][32 + lm] = w1.w;
    }
    __syncthreads();

    for (int k0 = 0; k0 < 256; k0 += 16) {
        int cur = (k0 >> 4) & 1, nxt = cur ^ 1;
        float4 av, w0, w1;
        bool more = (k0 + 16) < 256;
        if (more) {
            av = *(const float4*)(Ap  + k0 + 16);
            w0 = *(const float4*)(Wp0 + k0 + 16);
            w1 = *(const float4*)(Wp1 + k0 + 16);
        }
        #pragma unroll
        for (int k = 0; k < 16; k++) {
            float4 a = *(const float4*)&As[cur][k][ty * 4];
            ulonglong2 bb = *(const ulonglong2*)&Ws[cur][k][tx * 4];  // free pairs
            float am[4] = {a.x, a.y, a.z, a.w};
            #pragma unroll
            for (int i = 0; i < 4; i++) {
                u64 aa = pk(am[i], am[i]);
                accp[i][0] = fma2_(aa, bb.x, accp[i][0]);
                accp[i][1] = fma2_(aa, bb.y, accp[i][1]);
            }
        }
        if (more) {
            As[nxt][lk + 0][lm] = av.x; As[nxt][lk + 1][lm] = av.y;
            As[nxt][lk + 2][lm] = av.z; As[nxt][lk + 3][lm] = av.w;
            Ws[nxt][lk + 0][lm] = w0.x; Ws[nxt][lk + 1][lm] = w0.y;
            Ws[nxt][lk + 2][lm] = w0.z; Ws[nxt][lk + 3][lm] = w0.w;
            Ws[nxt][lk + 0][32 + lm] = w1.x; Ws[nxt][lk + 1][32 + lm] = w1.y;
            Ws[nxt][lk + 2][32 + lm] = w1.z; Ws[nxt][lk + 3][32 + lm] = w1.w;
            __syncthreads();
        }
    }

    int bb = m0 >> 8;
    int hh = (n0 >> 4) + (tx >> 2);
    int dd = (tx & 3) * 4;
    #pragma unroll
    for (int i = 0; i < 4; i++) {
        int r = (m0 & 255) + ty * 4 + i;
        float4 o;
        upk(accp[i][0], o.x, o.y);
        upk(accp[i][1], o.z, o.w);
        *(float4*)&O[((bb * H_ + hh) * NQ + r) * D_ + dd] = o;
    }
}

// ---------------------------------------------------------------------------
// Reduce-scatter over 32 lanes: input acc[8] packed u64 = 16 floats (d pairs).
// Returns full 32-lane sum for d = f(lane); every xor-1 lane pair agrees.
// ---------------------------------------------------------------------------
__device__ __forceinline__ float reduce16(const u64 acc[8], int lane, int& dOut)
{
    bool k16 = (lane & 16) == 0;
    u64 h[4];
    #pragma unroll
    for (int j = 0; j < 4; j++) {
        u64 send = k16 ? acc[4 + j] : acc[j];
        u64 recv = __shfl_xor_sync(0xffffffffu, send, 16);
        u64 mine = k16 ? acc[j] : acc[4 + j];
        h[j] = add2_(mine, recv);
    }
    bool k8 = (lane & 8) == 0;
    u64 g[2];
    #pragma unroll
    for (int j = 0; j < 2; j++) {
        u64 send = k8 ? h[2 + j] : h[j];
        u64 recv = __shfl_xor_sync(0xffffffffu, send, 8);
        u64 mine = k8 ? h[j] : h[2 + j];
        g[j] = add2_(mine, recv);
    }
    bool k4 = (lane & 4) == 0;
    {
        u64 send = k4 ? g[1] : g[0];
        u64 recv = __shfl_xor_sync(0xffffffffu, send, 4);
        u64 mine = k4 ? g[0] : g[1];
        g[0] = add2_(mine, recv);
    }
    float lo, hi; upk(g[0], lo, hi);
    bool k2 = (lane & 2) == 0;
    float send = k2 ? hi : lo;
    float recv = __shfl_xor_sync(0xffffffffu, send, 2);
    float s = (k2 ? lo : hi) + recv;
    s += __shfl_xor_sync(0xffffffffu, s, 1);
    dOut = ((lane & 16) >> 1) | ((lane & 8) >> 1) | ((lane & 4) >> 1) | ((lane & 2) >> 1);
    return s;
}

// ---------------------------------------------------------------------------
// Kernel B: fused scores + mixing-MLP + softmax + AV.
// One warp per TWO rows, phase 1 computed ROW-SEQUENTIALLY (one q array,
// reused) to cut the live-register peak that previously forced 80 regs;
// with the peak removed, (256,4) gives 64 regs / 4 blocks/SM / 32 warps.
// MLP identity: sum_m w2*relu(t_m) = A*dot + B*cost + [C] + sum (0.5w2)|t|;
// C and mix2_bias softmax-invariant (dropped); 1/sqrt(D) folded into w1a.
// ---------------------------------------------------------------------------
__global__ __launch_bounds__(256, 4) void attn_kernel(
    const float* __restrict__ cost_mat,
    const float* __restrict__ mix1_w,   // [16][2][32]
    const float* __restrict__ mix1_b,   // [16][32]
    const float* __restrict__ mix2_w,   // [16][32][1]
    float* __restrict__ out)            // [B][R][H*D]
{
    __shared__ __align__(16) float Ks[256][20];
    __shared__ __align__(16) float Vs[256][20];
    __shared__ u64   mlpp[32][4];       // (wx pair, wy pair, b1 pair, 0.5*w2 pair)
    __shared__ u64   ABs[2];            // packed (A,A), (B,B)

    int b = blockIdx.z, h = blockIdx.y, rt = blockIdx.x;
    int bh = b * H_ + h;
    int t = threadIdx.x;
    int lane = t & 31, w = t >> 5;
    int r0 = rt * 16 + w * 2;           // this warp handles rows r0, r0+1

    // ---- cooperative K/V tile staging ----
    {
        const float* Kg = g_K + bh * NQ * D_;
        const float* Vg = g_V + bh * NQ * D_;
        #pragma unroll
        for (int j = 0; j < 4; j++) {
            *(float4*)&Ks[t][j * 4] = *(const float4*)&Kg[t * D_ + j * 4];
            *(float4*)&Vs[t][j * 4] = *(const float4*)&Vg[t * D_ + j * 4];
        }
    }
    if (t < 32) {
        float wxv = mix1_w[h * 64 + t] * 0.25f;   // fold 1/sqrt(D)
        float wyv = mix1_w[h * 64 + 32 + t];
        float bzv = mix1_b[h * 32 + t];
        float hwv = mix2_w[h * 32 + t] * 0.5f;    // fold 0.5 of abs-relu identity
        mlpp[t][0] = pk(wxv, wxv);
        mlpp[t][1] = pk(wyv, wyv);
        mlpp[t][2] = pk(bzv, bzv);
        mlpp[t][3] = pk(hwv, hwv);
        float a  = hwv * wxv;
        float bb = hwv * wyv;
        #pragma unroll
        for (int o = 16; o; o >>= 1) {
            a  += __shfl_xor_sync(0xffffffffu, a, o);
            bb += __shfl_xor_sync(0xffffffffu, bb, o);
        }
        if (t == 0) { ABs[0] = pk(a, a); ABs[1] = pk(bb, bb); }
    }
    __syncthreads();

    // ---- Phase 1: raw dot scores, one row at a time (halved reg peak) ----
    u64 dp0[4], dp1[4];
    #pragma unroll
    for (int row = 0; row < 2; row++) {
        float q[16];
        {
            const float* Qg = g_Q + (bh * NQ + r0 + row) * D_;
            #pragma unroll
            for (int j = 0; j < 4; j++) {
                float4 a = *(const float4*)&Qg[j * 4];
                q[j*4+0] = a.x; q[j*4+1] = a.y; q[j*4+2] = a.z; q[j*4+3] = a.w;
            }
        }
        #pragma unroll
        for (int p = 0; p < 4; p++) {
            int ca = (2 * p) * 32 + lane;
            int cb = ca + 32;
            float sa = 0.f, sb = 0.f;
            #pragma unroll
            for (int j = 0; j < 4; j++) {
                float4 ka = *(const float4*)&Ks[ca][j * 4];
                float4 kb = *(const float4*)&Ks[cb][j * 4];
                sa = fmaf(q[j*4+0], ka.x, sa); sa = fmaf(q[j*4+1], ka.y, sa);
                sa = fmaf(q[j*4+2], ka.z, sa); sa = fmaf(q[j*4+3], ka.w, sa);
                sb = fmaf(q[j*4+0], kb.x, sb); sb = fmaf(q[j*4+1], kb.y, sb);
                sb = fmaf(q[j*4+2], kb.z, sb); sb = fmaf(q[j*4+3], kb.w, sb);
            }
            if (row == 0) dp0[p] = pk(sa, sb);
            else          dp1[p] = pk(sa, sb);
        }
    }

    // ---- cost loads ----
    const float* cr0 = cost_mat + (b * NQ + r0) * NQ;
    const float* cr1 = cr0 + NQ;
    u64 cp0[4], cp1[4];
    #pragma unroll
    for (int p = 0; p < 4; p++) {
        int ca = (2 * p) * 32 + lane;
        cp0[p] = pk(__ldg(cr0 + ca), __ldg(cr0 + ca + 32));
        cp1[p] = pk(__ldg(cr1 + ca), __ldg(cr1 + ca + 32));
    }

    // ---- Phase 2: mixing MLP (abs half only; linear half analytic) ----
    u64 A2 = ABs[0], B2 = ABs[1];
    u64 s0[4], s1[4];
    #pragma unroll
    for (int p = 0; p < 4; p++) {
        s0[p] = fma2_(B2, cp0[p], mul2_(A2, dp0[p]));
        s1[p] = fma2_(B2, cp1[p], mul2_(A2, dp1[p]));
    }
    #pragma unroll 4
    for (int m = 0; m < 32; m++) {
        ulonglong2 w01 = *(const ulonglong2*)&mlpp[m][0];
        ulonglong2 w23 = *(const ulonglong2*)&mlpp[m][2];
        u64 wxx = w01.x, wyy = w01.y, wzz = w23.x, hww = w23.y;
        #pragma unroll
        for (int p = 0; p < 4; p++) {
            u64 t0 = fma2_(wxx, dp0[p], fma2_(wyy, cp0[p], wzz));
            s0[p] = fma2_(hww, t0 & ABSM, s0[p]);
            u64 t1 = fma2_(wxx, dp1[p], fma2_(wyy, cp1[p], wzz));
            s1[p] = fma2_(hww, t1 & ABSM, s1[p]);
        }
    }

    // ---- Phase 3: softmax per row ----
    float sc0[8], sc1[8];
    #pragma unroll
    for (int p = 0; p < 4; p++) {
        upk(s0[p], sc0[2 * p], sc0[2 * p + 1]);
        upk(s1[p], sc1[2 * p], sc1[2 * p + 1]);
    }
    float mx0 = sc0[0], mx1 = sc1[0];
    #pragma unroll
    for (int i = 1; i < 8; i++) { mx0 = fmaxf(mx0, sc0[i]); mx1 = fmaxf(mx1, sc1[i]); }
    #pragma unroll
    for (int o = 16; o; o >>= 1) {
        mx0 = fmaxf(mx0, __shfl_xor_sync(0xffffffffu, mx0, o));
        mx1 = fmaxf(mx1, __shfl_xor_sync(0xffffffffu, mx1, o));
    }
    float sum0 = 0.f, sum1 = 0.f;
    #pragma unroll
    for (int i = 0; i < 8; i++) {
        sc0[i] = __expf(sc0[i] - mx0); sum0 += sc0[i];
        sc1[i] = __expf(sc1[i] - mx1); sum1 += sc1[i];
    }
    #pragma unroll
    for (int o = 16; o; o >>= 1) {
        sum0 += __shfl_xor_sync(0xffffffffu, sum0, o);
        sum1 += __shfl_xor_sync(0xffffffffu, sum1, o);
    }
    float inv0 = 1.f / sum0, inv1 = 1.f / sum1;

    // ---- Phase 4: AV accumulation (V pairs free via ulonglong2) ----
    u64 acc0[8], acc1[8];
    #pragma unroll
    for (int j = 0; j < 8; j++) { acc0[j] = 0ull; acc1[j] = 0ull; }
    #pragma unroll
    for (int i = 0; i < 8; i++) {
        int c = i * 32 + lane;
        u64 w0 = pk(sc0[i], sc0[i]);
        u64 w1 = pk(sc1[i], sc1[i]);
        #pragma unroll
        for (int j = 0; j < 4; j++) {
            ulonglong2 vv = *(const ulonglong2*)&Vs[c][j * 4];
            acc0[2 * j]     = fma2_(w0, vv.x, acc0[2 * j]);
            acc0[2 * j + 1] = fma2_(w0, vv.y, acc0[2 * j + 1]);
            acc1[2 * j]     = fma2_(w1, vv.x, acc1[2 * j]);
            acc1[2 * j + 1] = fma2_(w1, vv.y, acc1[2 * j + 1]);
        }
    }

    // ---- Phase 5: reduce-scatter epilogue ----
    int d0;
    float res0 = reduce16(acc0, lane, d0);
    int d1;
    float res1 = reduce16(acc1, lane, d1);
    if ((lane & 1) == 0) {
        out[(b * NQ + r0)     * (H_ * D_) + h * D_ + d0] = res0 * inv0;
        out[(b * NQ + r0 + 1) * (H_ * D_) + h * D_ + d1] = res1 * inv1;
    }
}

extern "C" void kernel_launch(void* const* d_in, const int* in_sizes, int n_in,
                              void* d_out, int out_size)
{
    const float* row_emb  = (const float*)d_in[0];
    const float* col_emb  = (const float*)d_in[1];
    const float* cost_mat = (const float*)d_in[2];
    const float* Wq       = (const float*)d_in[3];
    const float* Wk       = (const float*)d_in[4];
    const float* Wv       = (const float*)d_in[5];
    const float* m1w      = (const float*)d_in[6];
    const float* m1b      = (const float*)d_in[7];
    const float* m2w      = (const float*)d_in[8];
    // d_in[9] = mix2_bias: softmax-invariant, intentionally unused.
    float* out = (float*)d_out;

    dim3 gA(4, 32, 3);   // n-tiles x m-tiles x {Q,K,V} = 384 blocks
    qkv_kernel<<<gA, 128>>>(row_emb, col_emb, Wq, Wk, Wv);

    dim3 gB(16, 16, 4);  // 16-row tiles x heads x batch = 1024 blocks
    attn_kernel<<<gB, 256>>>(cost_mat, m1w, m1b, m2w, out);
}

// round 16
// speedup vs baseline: 1.1123x; 1.0382x over previous
#include <cuda_runtime.h>
#include <cuda_bf16.h>
#include <cstdint>

#define B_ 4
#define H_ 16
#define NQ 256
#define D_ 16

typedef unsigned long long u64;

#define ABSM 0x7FFFFFFF7FFFFFFFULL

// ---- packed f32x2 helpers (sm_100a) ---------------------------------------
__device__ __forceinline__ u64 pk(float a, float b) {
    u64 r; asm("mov.b64 %0, {%1,%2};" : "=l"(r) : "f"(a), "f"(b)); return r;
}
__device__ __forceinline__ void upk(u64 v, float& a, float& b) {
    asm("mov.b64 {%0,%1}, %2;" : "=f"(a), "=f"(b) : "l"(v));
}
__device__ __forceinline__ u64 fma2_(u64 a, u64 b, u64 c) {
    u64 r; asm("fma.rn.f32x2 %0, %1, %2, %3;" : "=l"(r) : "l"(a), "l"(b), "l"(c));
    return r;
}
__device__ __forceinline__ u64 add2_(u64 a, u64 b) {
    u64 r; asm("add.rn.f32x2 %0, %1, %2;" : "=l"(r) : "l"(a), "l"(b));
    return r;
}
__device__ __forceinline__ u64 mul2_(u64 a, u64 b) {
    u64 r; asm("mul.rn.f32x2 %0, %1, %2;" : "=l"(r) : "l"(a), "l"(b));
    return r;
}

// ---- tf32 split helpers ----------------------------------------------------
__device__ __forceinline__ void tf32split(float x, uint32_t& hi, uint32_t& lo) {
    asm("cvt.rna.tf32.f32 %0, %1;" : "=r"(hi) : "f"(x));
    float hf = __uint_as_float(hi);      // tf32 bits are a valid fp32 value
    float lf = x - hf;                   // exact in fp32
    asm("cvt.rna.tf32.f32 %0, %1;" : "=r"(lo) : "f"(lf));
}

__device__ __forceinline__ void mma_tf32(float* d, const uint32_t* a,
                                         uint32_t b0, uint32_t b1) {
    asm("mma.sync.aligned.m16n8k8.row.col.f32.tf32.tf32.f32 "
        "{%0,%1,%2,%3}, {%4,%5,%6,%7}, {%8,%9}, {%0,%1,%2,%3};"
        : "+f"(d[0]), "+f"(d[1]), "+f"(d[2]), "+f"(d[3])
        : "r"(a[0]), "r"(a[1]), "r"(a[2]), "r"(a[3]), "r"(b0), "r"(b1));
}

// Scratch for projected Q/K/V in [b][h][n][d] layout.
__device__ float g_Q[B_ * H_ * NQ * D_];
__device__ float g_K[B_ * H_ * NQ * D_];
__device__ float g_V[B_ * H_ * NQ * D_];

// ---------------------------------------------------------------------------
// Kernel A: QKV projections via split-tf32 tensor-core MMA.
// out[m, hd] = sum_e A[m, e] * W[hd, e]  (A row-major m x k; W row-major
// n x k == B col-major k x n, so mma row.col applies directly).
// Block tile 32(m) x 64(n), 128 threads = 4 warps (2m x 2n), warp tile
// 16 x 32 = 4 m16n8 fragments.  K-chunk 16 (2 k8 sub-steps), double-buffered
// smem staged row-major with pad 20 (fragment LDS pattern conflict-free).
// Split-tf32: D = Ahi@Bhi + Ahi@Blo + Alo@Bhi  (error ~2^-22).
// ---------------------------------------------------------------------------
__global__ __launch_bounds__(128) void qkv_kernel(
    const float* __restrict__ row_emb, const float* __restrict__ col_emb,
    const float* __restrict__ Wq, const float* __restrict__ Wk,
    const float* __restrict__ Wv)
{
    __shared__ __align__(16) float As2[2][32][20];
    __shared__ __align__(16) float Ws2[2][64][20];

    const float* A; const float* W; float* O;
    int z = blockIdx.z;
    if (z == 0)      { A = row_emb; W = Wq; O = g_Q; }
    else if (z == 1) { A = col_emb; W = Wk; O = g_K; }
    else             { A = col_emb; W = Wv; O = g_V; }

    int m0 = blockIdx.y * 32;
    int n0 = blockIdx.x * 64;
    int t  = threadIdx.x;
    int wid = t >> 5, lane = t & 31;
    int g = lane >> 2, tq = lane & 3;    // fragment group / thread-in-group
    int wm = (wid >> 1) * 16;            // warp m-offset within block tile
    int wn = (wid & 1) * 32;             // warp n-offset within block tile

    // Staging map: thread -> (row, k-quad).
    int srow = t >> 2;                   // 0..31
    int skq  = (t & 3) * 4;              // 0,4,8,12
    const float* ApS  = &A[(m0 + srow) * 256 + skq];
    const float* WpS0 = &W[(n0 + srow) * 256 + skq];
    const float* WpS1 = &W[(n0 + 32 + srow) * 256 + skq];

    float acc[4][4];                     // [n-tile][c0..c3]
    #pragma unroll
    for (int i = 0; i < 4; i++)
        #pragma unroll
        for (int j = 0; j < 4; j++) acc[i][j] = 0.f;

    // Prologue: fill stage 0.
    {
        float4 av = *(const float4*)ApS;
        float4 w0 = *(const float4*)WpS0;
        float4 w1 = *(const float4*)WpS1;
        *(float4*)&As2[0][srow][skq]      = av;
        *(float4*)&Ws2[0][srow][skq]      = w0;
        *(float4*)&Ws2[0][32 + srow][skq] = w1;
    }
    __syncthreads();

    for (int k0 = 0; k0 < 256; k0 += 16) {
        int cur = (k0 >> 4) & 1, nxt = cur ^ 1;
        float4 av, w0, w1;
        bool more = (k0 + 16) < 256;
        if (more) {
            av = *(const float4*)(ApS  + k0 + 16);
            w0 = *(const float4*)(WpS0 + k0 + 16);
            w1 = *(const float4*)(WpS1 + k0 + 16);
        }
        #pragma unroll
        for (int ks = 0; ks < 2; ks++) {
            int kb = ks * 8;
            // A fragment (m16k8): a0=(g,tq) a1=(g+8,tq) a2=(g,tq+4) a3=(g+8,tq+4)
            float af[4];
            af[0] = As2[cur][wm + g    ][kb + tq];
            af[1] = As2[cur][wm + g + 8][kb + tq];
            af[2] = As2[cur][wm + g    ][kb + tq + 4];
            af[3] = As2[cur][wm + g + 8][kb + tq + 4];
            uint32_t ah[4], al[4];
            #pragma unroll
            for (int i = 0; i < 4; i++) tf32split(af[i], ah[i], al[i]);

            #pragma unroll
            for (int nt = 0; nt < 4; nt++) {
                // B fragment (k8n8, col-major): b0=(k=tq, n=g), b1=(k=tq+4, n=g)
                float bf0 = Ws2[cur][wn + nt * 8 + g][kb + tq];
                float bf1 = Ws2[cur][wn + nt * 8 + g][kb + tq + 4];
                uint32_t bh0, bl0, bh1, bl1;
                tf32split(bf0, bh0, bl0);
                tf32split(bf1, bh1, bl1);
                mma_tf32(acc[nt], ah, bh0, bh1);   // Ahi @ Bhi
                mma_tf32(acc[nt], ah, bl0, bl1);   // Ahi @ Blo
                mma_tf32(acc[nt], al, bh0, bh1);   // Alo @ Bhi
            }
        }
        if (more) {
            *(float4*)&As2[nxt][srow][skq]      = av;
            *(float4*)&Ws2[nxt][srow][skq]      = w0;
            *(float4*)&Ws2[nxt][32 + srow][skq] = w1;
            __syncthreads();
        }
    }

    // Epilogue: C fragment c0=(g, 2tq) c1=(g, 2tq+1) c2=(g+8, 2tq) c3=(g+8, 2tq+1)
    int bb = m0 >> 8;
    int rA = (m0 & 255) + wm + g;
    #pragma unroll
    for (int nt = 0; nt < 4; nt++) {
        int ng = n0 + wn + nt * 8;       // 8-col group, stays in one head
        int hh = ng >> 4;
        int dd = (ng & 15) + 2 * tq;
        float2 c01 = make_float2(acc[nt][0], acc[nt][1]);
        float2 c23 = make_float2(acc[nt][2], acc[nt][3]);
        *(float2*)&O[((bb * H_ + hh) * NQ + rA)     * D_ + dd] = c01;
        *(float2*)&O[((bb * H_ + hh) * NQ + rA + 8) * D_ + dd] = c23;
    }
}

// ---------------------------------------------------------------------------
// Reduce-scatter over 32 lanes: input acc[8] packed u64 = 16 floats (d pairs).
// Returns full 32-lane sum for d = f(lane); every xor-1 lane pair agrees.
// ---------------------------------------------------------------------------
__device__ __forceinline__ float reduce16(const u64 acc[8], int lane, int& dOut)
{
    bool k16 = (lane & 16) == 0;
    u64 h[4];
    #pragma unroll
    for (int j = 0; j < 4; j++) {
        u64 send = k16 ? acc[4 + j] : acc[j];
        u64 recv = __shfl_xor_sync(0xffffffffu, send, 16);
        u64 mine = k16 ? acc[j] : acc[4 + j];
        h[j] = add2_(mine, recv);
    }
    bool k8 = (lane & 8) == 0;
    u64 g[2];
    #pragma unroll
    for (int j = 0; j < 2; j++) {
        u64 send = k8 ? h[2 + j] : h[j];
        u64 recv = __shfl_xor_sync(0xffffffffu, send, 8);
        u64 mine = k8 ? h[j] : h[2 + j];
        g[j] = add2_(mine, recv);
    }
    bool k4 = (lane & 4) == 0;
    {
        u64 send = k4 ? g[1] : g[0];
        u64 recv = __shfl_xor_sync(0xffffffffu, send, 4);
        u64 mine = k4 ? g[0] : g[1];
        g[0] = add2_(mine, recv);
    }
    float lo, hi; upk(g[0], lo, hi);
    bool k2 = (lane & 2) == 0;
    float send = k2 ? hi : lo;
    float recv = __shfl_xor_sync(0xffffffffu, send, 2);
    float s = (k2 ? lo : hi) + recv;
    s += __shfl_xor_sync(0xffffffffu, s, 1);
    dOut = ((lane & 16) >> 1) | ((lane & 8) >> 1) | ((lane & 4) >> 1) | ((lane & 2) >> 1);
    return s;
}

// ---------------------------------------------------------------------------
// Kernel B: fused scores + mixing-MLP + softmax + AV.  (R10 configuration —
// best measured, 80 regs / 3 blocks/SM.)  One warp per TWO rows.
// MLP identity: sum_m w2*relu(t_m) = A*dot + B*cost + [C] + sum (0.5w2)|t|;
// C and mix2_bias softmax-invariant (dropped); 1/sqrt(D) folded into w1a.
// ---------------------------------------------------------------------------
__global__ __launch_bounds__(256, 3) void attn_kernel(
    const float* __restrict__ cost_mat,
    const float* __restrict__ mix1_w,   // [16][2][32]
    const float* __restrict__ mix1_b,   // [16][32]
    const float* __restrict__ mix2_w,   // [16][32][1]
    float* __restrict__ out)            // [B][R][H*D]
{
    __shared__ __align__(16) float Ks[256][20];
    __shared__ __align__(16) float Vs[256][20];
    __shared__ u64   mlpp[32][4];       // (wx pair, wy pair, b1 pair, 0.5*w2 pair)
    __shared__ u64   ABs[2];            // packed (A,A), (B,B)

    int b = blockIdx.z, h = blockIdx.y, rt = blockIdx.x;
    int bh = b * H_ + h;
    int t = threadIdx.x;
    int lane = t & 31, w = t >> 5;
    int r0 = rt * 16 + w * 2;           // this warp handles rows r0, r0+1

    // ---- cooperative K/V tile staging ----
    {
        const float* Kg = g_K + bh * NQ * D_;
        const float* Vg = g_V + bh * NQ * D_;
        #pragma unroll
        for (int j = 0; j < 4; j++) {
            *(float4*)&Ks[t][j * 4] = *(const float4*)&Kg[t * D_ + j * 4];
            *(float4*)&Vs[t][j * 4] = *(const float4*)&Vg[t * D_ + j * 4];
        }
    }
    if (t < 32) {
        float wxv = mix1_w[h * 64 + t] * 0.25f;   // fold 1/sqrt(D)
        float wyv = mix1_w[h * 64 + 32 + t];
        float bzv = mix1_b[h * 32 + t];
        float hwv = mix2_w[h * 32 + t] * 0.5f;    // fold 0.5 of abs-relu identity
        mlpp[t][0] = pk(wxv, wxv);
        mlpp[t][1] = pk(wyv, wyv);
        mlpp[t][2] = pk(bzv, bzv);
        mlpp[t][3] = pk(hwv, hwv);
        float a  = hwv * wxv;
        float bb = hwv * wyv;
        #pragma unroll
        for (int o = 16; o; o >>= 1) {
            a  += __shfl_xor_sync(0xffffffffu, a, o);
            bb += __shfl_xor_sync(0xffffffffu, bb, o);
        }
        if (t == 0) { ABs[0] = pk(a, a); ABs[1] = pk(bb, bb); }
    }
    __syncthreads();

    // ---- Phase 1: raw dot scores (scale folded into wx) ----
    float q0[16], q1[16];
    {
        const float* Qg = g_Q + (bh * NQ + r0) * D_;
        #pragma unroll
        for (int j = 0; j < 4; j++) {
            float4 a = *(const float4*)&Qg[j * 4];
            float4 c = *(const float4*)&Qg[16 + j * 4];
            q0[j*4+0] = a.x; q0[j*4+1] = a.y; q0[j*4+2] = a.z; q0[j*4+3] = a.w;
            q1[j*4+0] = c.x; q1[j*4+1] = c.y; q1[j*4+2] = c.z; q1[j*4+3] = c.w;
        }
    }
    u64 dp0[4], dp1[4];
    #pragma unroll
    for (int p = 0; p < 4; p++) {
        int ca = (2 * p) * 32 + lane;
        int cb = ca + 32;
        float sa0 = 0.f, sa1 = 0.f, sb0 = 0.f, sb1 = 0.f;
        #pragma unroll
        for (int j = 0; j < 4; j++) {
            float4 ka = *(const float4*)&Ks[ca][j * 4];
            float4 kb = *(const float4*)&Ks[cb][j * 4];
            sa0 = fmaf(q0[j*4+0], ka.x, sa0); sa0 = fmaf(q0[j*4+1], ka.y, sa0);
            sa0 = fmaf(q0[j*4+2], ka.z, sa0); sa0 = fmaf(q0[j*4+3], ka.w, sa0);
            sa1 = fmaf(q1[j*4+0], ka.x, sa1); sa1 = fmaf(q1[j*4+1], ka.y, sa1);
            sa1 = fmaf(q1[j*4+2], ka.z, sa1); sa1 = fmaf(q1[j*4+3], ka.w, sa1);
            sb0 = fmaf(q0[j*4+0], kb.x, sb0); sb0 = fmaf(q0[j*4+1], kb.y, sb0);
            sb0 = fmaf(q0[j*4+2], kb.z, sb0); sb0 = fmaf(q0[j*4+3], kb.w, sb0);
            sb1 = fmaf(q1[j*4+0], kb.x, sb1); sb1 = fmaf(q1[j*4+1], kb.y, sb1);
            sb1 = fmaf(q1[j*4+2], kb.z, sb1); sb1 = fmaf(q1[j*4+3], kb.w, sb1);
        }
        dp0[p] = pk(sa0, sb0);
        dp1[p] = pk(sa1, sb1);
    }

    // ---- cost loads (after phase 1 so q regs can retire first) ----
    const float* cr0 = cost_mat + (b * NQ + r0) * NQ;
    const float* cr1 = cr0 + NQ;
    u64 cp0[4], cp1[4];
    #pragma unroll
    for (int p = 0; p < 4; p++) {
        int ca = (2 * p) * 32 + lane;
        cp0[p] = pk(__ldg(cr0 + ca), __ldg(cr0 + ca + 32));
        cp1[p] = pk(__ldg(cr1 + ca), __ldg(cr1 + ca + 32));
    }

    // ---- Phase 2: mixing MLP (abs half only; linear half analytic) ----
    u64 A2 = ABs[0], B2 = ABs[1];
    u64 s0[4], s1[4];
    #pragma unroll
    for (int p = 0; p < 4; p++) {
        s0[p] = fma2_(B2, cp0[p], mul2_(A2, dp0[p]));
        s1[p] = fma2_(B2, cp1[p], mul2_(A2, dp1[p]));
    }
    #pragma unroll 4
    for (int m = 0; m < 32; m++) {
        ulonglong2 w01 = *(const ulonglong2*)&mlpp[m][0];
        ulonglong2 w23 = *(const ulonglong2*)&mlpp[m][2];
        u64 wxx = w01.x, wyy = w01.y, wzz = w23.x, hww = w23.y;
        #pragma unroll
        for (int p = 0; p < 4; p++) {
            u64 t0 = fma2_(wxx, dp0[p], fma2_(wyy, cp0[p], wzz));
            s0[p] = fma2_(hww, t0 & ABSM, s0[p]);
            u64 t1 = fma2_(wxx, dp1[p], fma2_(wyy, cp1[p], wzz));
            s1[p] = fma2_(hww, t1 & ABSM, s1[p]);
        }
    }

    // ---- Phase 3: softmax per row ----
    float sc0[8], sc1[8];
    #pragma unroll
    for (int p = 0; p < 4; p++) {
        upk(s0[p], sc0[2 * p], sc0[2 * p + 1]);
        upk(s1[p], sc1[2 * p], sc1[2 * p + 1]);
    }
    float mx0 = sc0[0], mx1 = sc1[0];
    #pragma unroll
    for (int i = 1; i < 8; i++) { mx0 = fmaxf(mx0, sc0[i]); mx1 = fmaxf(mx1, sc1[i]); }
    #pragma unroll
    for (int o = 16; o; o >>= 1) {
        mx0 = fmaxf(mx0, __shfl_xor_sync(0xffffffffu, mx0, o));
        mx1 = fmaxf(mx1, __shfl_xor_sync(0xffffffffu, mx1, o));
    }
    float sum0 = 0.f, sum1 = 0.f;
    #pragma unroll
    for (int i = 0; i < 8; i++) {
        sc0[i] = __expf(sc0[i] - mx0); sum0 += sc0[i];
        sc1[i] = __expf(sc1[i] - mx1); sum1 += sc1[i];
    }
    #pragma unroll
    for (int o = 16; o; o >>= 1) {
        sum0 += __shfl_xor_sync(0xffffffffu, sum0, o);
        sum1 += __shfl_xor_sync(0xffffffffu, sum1, o);
    }
    float inv0 = 1.f / sum0, inv1 = 1.f / sum1;

    // ---- Phase 4: AV accumulation (V pairs free via ulonglong2) ----
    u64 acc0[8], acc1[8];
    #pragma unroll
    for (int j = 0; j < 8; j++) { acc0[j] = 0ull; acc1[j] = 0ull; }
    #pragma unroll
    for (int i = 0; i < 8; i++) {
        int c = i * 32 + lane;
        u64 w0 = pk(sc0[i], sc0[i]);
        u64 w1 = pk(sc1[i], sc1[i]);
        #pragma unroll
        for (int j = 0; j < 4; j++) {
            ulonglong2 vv = *(const ulonglong2*)&Vs[c][j * 4];
            acc0[2 * j]     = fma2_(w0, vv.x, acc0[2 * j]);
            acc0[2 * j + 1] = fma2_(w0, vv.y, acc0[2 * j + 1]);
            acc1[2 * j]     = fma2_(w1, vv.x, acc1[2 * j]);
            acc1[2 * j + 1] = fma2_(w1, vv.y, acc1[2 * j + 1]);
        }
    }

    // ---- Phase 5: reduce-scatter epilogue ----
    int d0;
    float res0 = reduce16(acc0, lane, d0);
    int d1;
    float res1 = reduce16(acc1, lane, d1);
    if ((lane & 1) == 0) {
        out[(b * NQ + r0)     * (H_ * D_) + h * D_ + d0] = res0 * inv0;
        out[(b * NQ + r0 + 1) * (H_ * D_) + h * D_ + d1] = res1 * inv1;
    }
}

extern "C" void kernel_launch(void* const* d_in, const int* in_sizes, int n_in,
                              void* d_out, int out_size)
{
    const float* row_emb  = (const float*)d_in[0];
    const float* col_emb  = (const float*)d_in[1];
    const float* cost_mat = (const float*)d_in[2];
    const float* Wq       = (const float*)d_in[3];
    const float* Wk       = (const float*)d_in[4];
    const float* Wv       = (const float*)d_in[5];
    const float* m1w      = (const float*)d_in[6];
    const float* m1b      = (const float*)d_in[7];
    const float* m2w      = (const float*)d_in[8];
    // d_in[9] = mix2_bias: softmax-invariant, intentionally unused.
    float* out = (float*)d_out;

    dim3 gA(4, 32, 3);   // n-tiles x m-tiles x {Q,K,V} = 384 blocks
    qkv_kernel<<<gA, 128>>>(row_emb, col_emb, Wq, Wk, Wv);

    dim3 gB(16, 16, 4);  // 16-row tiles x heads x batch = 1024 blocks
    attn_kernel<<<gB, 256>>>(cost_mat, m1w, m1b, m2w, out);
}

// round 17
// speedup vs baseline: 1.1510x; 1.0348x over previous
#include <cuda_runtime.h>
#include <cuda_bf16.h>
#include <cstdint>

#define B_ 4
#define H_ 16
#define NQ 256
#define D_ 16

typedef unsigned long long u64;

#define ABSM 0x7FFFFFFF7FFFFFFFULL

// ---- packed f32x2 helpers (sm_100a) ---------------------------------------
__device__ __forceinline__ u64 pk(float a, float b) {
    u64 r; asm("mov.b64 %0, {%1,%2};" : "=l"(r) : "f"(a), "f"(b)); return r;
}
__device__ __forceinline__ void upk(u64 v, float& a, float& b) {
    asm("mov.b64 {%0,%1}, %2;" : "=f"(a), "=f"(b) : "l"(v));
}
__device__ __forceinline__ u64 fma2_(u64 a, u64 b, u64 c) {
    u64 r; asm("fma.rn.f32x2 %0, %1, %2, %3;" : "=l"(r) : "l"(a), "l"(b), "l"(c));
    return r;
}
__device__ __forceinline__ u64 add2_(u64 a, u64 b) {
    u64 r; asm("add.rn.f32x2 %0, %1, %2;" : "=l"(r) : "l"(a), "l"(b));
    return r;
}
__device__ __forceinline__ u64 mul2_(u64 a, u64 b) {
    u64 r; asm("mul.rn.f32x2 %0, %1, %2;" : "=l"(r) : "l"(a), "l"(b));
    return r;
}

// ---- tf32 split helpers ----------------------------------------------------
__device__ __forceinline__ void tf32split(float x, uint32_t& hi, uint32_t& lo) {
    asm("cvt.rna.tf32.f32 %0, %1;" : "=r"(hi) : "f"(x));
    float hf = __uint_as_float(hi);      // tf32 bits are a valid fp32 value
    float lf = x - hf;                   // exact in fp32
    asm("cvt.rna.tf32.f32 %0, %1;" : "=r"(lo) : "f"(lf));
}

__device__ __forceinline__ void mma_tf32(float* d, const uint32_t* a,
                                         uint32_t b0, uint32_t b1) {
    asm("mma.sync.aligned.m16n8k8.row.col.f32.tf32.tf32.f32 "
        "{%0,%1,%2,%3}, {%4,%5,%6,%7}, {%8,%9}, {%0,%1,%2,%3};"
        : "+f"(d[0]), "+f"(d[1]), "+f"(d[2]), "+f"(d[3])
        : "r"(a[0]), "r"(a[1]), "r"(a[2]), "r"(a[3]), "r"(b0), "r"(b1));
}

// Scratch for projected Q/K/V in [b][h][n][d] layout.
__device__ float g_Q[B_ * H_ * NQ * D_];
__device__ float g_K[B_ * H_ * NQ * D_];
__device__ float g_V[B_ * H_ * NQ * D_];

// ---------------------------------------------------------------------------
// Kernel A: QKV projections via split-tf32 tensor-core MMA.  (R16 config.)
// out[m, hd] = sum_e A[m, e] * W[hd, e]  (A row-major m x k; W row-major
// n x k == B col-major k x n, so mma row.col applies directly).
// Block tile 32(m) x 64(n), 128 threads = 4 warps (2m x 2n), warp tile
// 16 x 32 = 4 m16n8 fragments.  K-chunk 16 (2 k8 sub-steps), double-buffered
// smem staged row-major with pad 20.  Split-tf32: D = Ahi@Bhi+Ahi@Blo+Alo@Bhi.
// ---------------------------------------------------------------------------
__global__ __launch_bounds__(128) void qkv_kernel(
    const float* __restrict__ row_emb, const float* __restrict__ col_emb,
    const float* __restrict__ Wq, const float* __restrict__ Wk,
    const float* __restrict__ Wv)
{
    __shared__ __align__(16) float As2[2][32][20];
    __shared__ __align__(16) float Ws2[2][64][20];

    const float* A; const float* W; float* O;
    int z = blockIdx.z;
    if (z == 0)      { A = row_emb; W = Wq; O = g_Q; }
    else if (z == 1) { A = col_emb; W = Wk; O = g_K; }
    else             { A = col_emb; W = Wv; O = g_V; }

    int m0 = blockIdx.y * 32;
    int n0 = blockIdx.x * 64;
    int t  = threadIdx.x;
    int wid = t >> 5, lane = t & 31;
    int g = lane >> 2, tq = lane & 3;    // fragment group / thread-in-group
    int wm = (wid >> 1) * 16;            // warp m-offset within block tile
    int wn = (wid & 1) * 32;             // warp n-offset within block tile

    // Staging map: thread -> (row, k-quad).
    int srow = t >> 2;                   // 0..31
    int skq  = (t & 3) * 4;              // 0,4,8,12
    const float* ApS  = &A[(m0 + srow) * 256 + skq];
    const float* WpS0 = &W[(n0 + srow) * 256 + skq];
    const float* WpS1 = &W[(n0 + 32 + srow) * 256 + skq];

    float acc[4][4];                     // [n-tile][c0..c3]
    #pragma unroll
    for (int i = 0; i < 4; i++)
        #pragma unroll
        for (int j = 0; j < 4; j++) acc[i][j] = 0.f;

    // Prologue: fill stage 0.
    {
        float4 av = *(const float4*)ApS;
        float4 w0 = *(const float4*)WpS0;
        float4 w1 = *(const float4*)WpS1;
        *(float4*)&As2[0][srow][skq]      = av;
        *(float4*)&Ws2[0][srow][skq]      = w0;
        *(float4*)&Ws2[0][32 + srow][skq] = w1;
    }
    __syncthreads();

    for (int k0 = 0; k0 < 256; k0 += 16) {
        int cur = (k0 >> 4) & 1, nxt = cur ^ 1;
        float4 av, w0, w1;
        bool more = (k0 + 16) < 256;
        if (more) {
            av = *(const float4*)(ApS  + k0 + 16);
            w0 = *(const float4*)(WpS0 + k0 + 16);
            w1 = *(const float4*)(WpS1 + k0 + 16);
        }
        #pragma unroll
        for (int ks = 0; ks < 2; ks++) {
            int kb = ks * 8;
            // A fragment (m16k8): a0=(g,tq) a1=(g+8,tq) a2=(g,tq+4) a3=(g+8,tq+4)
            float af[4];
            af[0] = As2[cur][wm + g    ][kb + tq];
            af[1] = As2[cur][wm + g + 8][kb + tq];
            af[2] = As2[cur][wm + g    ][kb + tq + 4];
            af[3] = As2[cur][wm + g + 8][kb + tq + 4];
            uint32_t ah[4], al[4];
            #pragma unroll
            for (int i = 0; i < 4; i++) tf32split(af[i], ah[i], al[i]);

            #pragma unroll
            for (int nt = 0; nt < 4; nt++) {
                // B fragment (k8n8, col-major): b0=(k=tq, n=g), b1=(k=tq+4, n=g)
                float bf0 = Ws2[cur][wn + nt * 8 + g][kb + tq];
                float bf1 = Ws2[cur][wn + nt * 8 + g][kb + tq + 4];
                uint32_t bh0, bl0, bh1, bl1;
                tf32split(bf0, bh0, bl0);
                tf32split(bf1, bh1, bl1);
                mma_tf32(acc[nt], ah, bh0, bh1);   // Ahi @ Bhi
                mma_tf32(acc[nt], ah, bl0, bl1);   // Ahi @ Blo
                mma_tf32(acc[nt], al, bh0, bh1);   // Alo @ Bhi
            }
        }
        if (more) {
            *(float4*)&As2[nxt][srow][skq]      = av;
            *(float4*)&Ws2[nxt][srow][skq]      = w0;
            *(float4*)&Ws2[nxt][32 + srow][skq] = w1;
            __syncthreads();
        }
    }

    // Epilogue: C fragment c0=(g, 2tq) c1=(g, 2tq+1) c2=(g+8, 2tq) c3=(g+8, 2tq+1)
    int bb = m0 >> 8;
    int rA = (m0 & 255) + wm + g;
    #pragma unroll
    for (int nt = 0; nt < 4; nt++) {
        int ng = n0 + wn + nt * 8;       // 8-col group, stays in one head
        int hh = ng >> 4;
        int dd = (ng & 15) + 2 * tq;
        float2 c01 = make_float2(acc[nt][0], acc[nt][1]);
        float2 c23 = make_float2(acc[nt][2], acc[nt][3]);
        *(float2*)&O[((bb * H_ + hh) * NQ + rA)     * D_ + dd] = c01;
        *(float2*)&O[((bb * H_ + hh) * NQ + rA + 8) * D_ + dd] = c23;
    }
}

// ---------------------------------------------------------------------------
// Reduce-scatter over 32 lanes: input acc[8] packed u64 = 16 floats (d pairs).
// Returns full 32-lane sum for d = f(lane); every xor-1 lane pair agrees.
// ---------------------------------------------------------------------------
__device__ __forceinline__ float reduce16(const u64 acc[8], int lane, int& dOut)
{
    bool k16 = (lane & 16) == 0;
    u64 h[4];
    #pragma unroll
    for (int j = 0; j < 4; j++) {
        u64 send = k16 ? acc[4 + j] : acc[j];
        u64 recv = __shfl_xor_sync(0xffffffffu, send, 16);
        u64 mine = k16 ? acc[j] : acc[4 + j];
        h[j] = add2_(mine, recv);
    }
    bool k8 = (lane & 8) == 0;
    u64 g[2];
    #pragma unroll
    for (int j = 0; j < 2; j++) {
        u64 send = k8 ? h[2 + j] : h[j];
        u64 recv = __shfl_xor_sync(0xffffffffu, send, 8);
        u64 mine = k8 ? h[j] : h[2 + j];
        g[j] = add2_(mine, recv);
    }
    bool k4 = (lane & 4) == 0;
    {
        u64 send = k4 ? g[1] : g[0];
        u64 recv = __shfl_xor_sync(0xffffffffu, send, 4);
        u64 mine = k4 ? g[0] : g[1];
        g[0] = add2_(mine, recv);
    }
    float lo, hi; upk(g[0], lo, hi);
    bool k2 = (lane & 2) == 0;
    float send = k2 ? hi : lo;
    float recv = __shfl_xor_sync(0xffffffffu, send, 2);
    float s = (k2 ? lo : hi) + recv;
    s += __shfl_xor_sync(0xffffffffu, s, 1);
    dOut = ((lane & 16) >> 1) | ((lane & 8) >> 1) | ((lane & 4) >> 1) | ((lane & 2) >> 1);
    return s;
}

// ---------------------------------------------------------------------------
// Kernel B: fused scores + mixing-MLP + softmax + AV.  (R16 base, one change:
// cost-matrix LDGs are ISSUED before __syncthreads, so their latency is
// hidden under the barrier + all of phase 1 instead of stalling phase 2.)
// One warp per TWO rows.  MLP identity:
//   sum_m w2*relu(t_m) = A*dot + B*cost + [C] + sum_m (0.5*w2_m)*|t_m|
// C and mix2_bias softmax-invariant (dropped); 1/sqrt(D) folded into w1a.
// ---------------------------------------------------------------------------
__global__ __launch_bounds__(256, 3) void attn_kernel(
    const float* __restrict__ cost_mat,
    const float* __restrict__ mix1_w,   // [16][2][32]
    const float* __restrict__ mix1_b,   // [16][32]
    const float* __restrict__ mix2_w,   // [16][32][1]
    float* __restrict__ out)            // [B][R][H*D]
{
    __shared__ __align__(16) float Ks[256][20];
    __shared__ __align__(16) float Vs[256][20];
    __shared__ u64   mlpp[32][4];       // (wx pair, wy pair, b1 pair, 0.5*w2 pair)
    __shared__ u64   ABs[2];            // packed (A,A), (B,B)

    int b = blockIdx.z, h = blockIdx.y, rt = blockIdx.x;
    int bh = b * H_ + h;
    int t = threadIdx.x;
    int lane = t & 31, w = t >> 5;
    int r0 = rt * 16 + w * 2;           // this warp handles rows r0, r0+1

    // ---- cooperative K/V tile staging ----
    {
        const float* Kg = g_K + bh * NQ * D_;
        const float* Vg = g_V + bh * NQ * D_;
        #pragma unroll
        for (int j = 0; j < 4; j++) {
            *(float4*)&Ks[t][j * 4] = *(const float4*)&Kg[t * D_ + j * 4];
            *(float4*)&Vs[t][j * 4] = *(const float4*)&Vg[t * D_ + j * 4];
        }
    }
    if (t < 32) {
        float wxv = mix1_w[h * 64 + t] * 0.25f;   // fold 1/sqrt(D)
        float wyv = mix1_w[h * 64 + 32 + t];
        float bzv = mix1_b[h * 32 + t];
        float hwv = mix2_w[h * 32 + t] * 0.5f;    // fold 0.5 of abs-relu identity
        mlpp[t][0] = pk(wxv, wxv);
        mlpp[t][1] = pk(wyv, wyv);
        mlpp[t][2] = pk(bzv, bzv);
        mlpp[t][3] = pk(hwv, hwv);
        float a  = hwv * wxv;
        float bb = hwv * wyv;
        #pragma unroll
        for (int o = 16; o; o >>= 1) {
            a  += __shfl_xor_sync(0xffffffffu, a, o);
            bb += __shfl_xor_sync(0xffffffffu, bb, o);
        }
        if (t == 0) { ABs[0] = pk(a, a); ABs[1] = pk(bb, bb); }
    }

    // ---- cost loads ISSUED HERE: in flight across the barrier + phase 1 ----
    const float* cr0 = cost_mat + (b * NQ + r0) * NQ;
    const float* cr1 = cr0 + NQ;
    u64 cp0[4], cp1[4];
    #pragma unroll
    for (int p = 0; p < 4; p++) {
        int ca = (2 * p) * 32 + lane;
        cp0[p] = pk(__ldg(cr0 + ca), __ldg(cr0 + ca + 32));
        cp1[p] = pk(__ldg(cr1 + ca), __ldg(cr1 + ca + 32));
    }
    __syncthreads();

    // ---- Phase 1: raw dot scores (scale folded into wx) ----
    float q0[16], q1[16];
    {
        const float* Qg = g_Q + (bh * NQ + r0) * D_;
        #pragma unroll
        for (int j = 0; j < 4; j++) {
            float4 a = *(const float4*)&Qg[j * 4];
            float4 c = *(const float4*)&Qg[16 + j * 4];
            q0[j*4+0] = a.x; q0[j*4+1] = a.y; q0[j*4+2] = a.z; q0[j*4+3] = a.w;
            q1[j*4+0] = c.x; q1[j*4+1] = c.y; q1[j*4+2] = c.z; q1[j*4+3] = c.w;
        }
    }
    u64 dp0[4], dp1[4];
    #pragma unroll
    for (int p = 0; p < 4; p++) {
        int ca = (2 * p) * 32 + lane;
        int cb = ca + 32;
        float sa0 = 0.f, sa1 = 0.f, sb0 = 0.f, sb1 = 0.f;
        #pragma unroll
        for (int j = 0; j < 4; j++) {
            float4 ka = *(const float4*)&Ks[ca][j * 4];
            float4 kb = *(const float4*)&Ks[cb][j * 4];
            sa0 = fmaf(q0[j*4+0], ka.x, sa0); sa0 = fmaf(q0[j*4+1], ka.y, sa0);
            sa0 = fmaf(q0[j*4+2], ka.z, sa0); sa0 = fmaf(q0[j*4+3], ka.w, sa0);
            sa1 = fmaf(q1[j*4+0], ka.x, sa1); sa1 = fmaf(q1[j*4+1], ka.y, sa1);
            sa1 = fmaf(q1[j*4+2], ka.z, sa1); sa1 = fmaf(q1[j*4+3], ka.w, sa1);
            sb0 = fmaf(q0[j*4+0], kb.x, sb0); sb0 = fmaf(q0[j*4+1], kb.y, sb0);
            sb0 = fmaf(q0[j*4+2], kb.z, sb0); sb0 = fmaf(q0[j*4+3], kb.w, sb0);
            sb1 = fmaf(q1[j*4+0], kb.x, sb1); sb1 = fmaf(q1[j*4+1], kb.y, sb1);
            sb1 = fmaf(q1[j*4+2], kb.z, sb1); sb1 = fmaf(q1[j*4+3], kb.w, sb1);
        }
        dp0[p] = pk(sa0, sb0);
        dp1[p] = pk(sa1, sb1);
    }

    // ---- Phase 2: mixing MLP (abs half only; linear half analytic) ----
    u64 A2 = ABs[0], B2 = ABs[1];
    u64 s0[4], s1[4];
    #pragma unroll
    for (int p = 0; p < 4; p++) {
        s0[p] = fma2_(B2, cp0[p], mul2_(A2, dp0[p]));
        s1[p] = fma2_(B2, cp1[p], mul2_(A2, dp1[p]));
    }
    #pragma unroll 4
    for (int m = 0; m < 32; m++) {
        ulonglong2 w01 = *(const ulonglong2*)&mlpp[m][0];
        ulonglong2 w23 = *(const ulonglong2*)&mlpp[m][2];
        u64 wxx = w01.x, wyy = w01.y, wzz = w23.x, hww = w23.y;
        #pragma unroll
        for (int p = 0; p < 4; p++) {
            u64 t0 = fma2_(wxx, dp0[p], fma2_(wyy, cp0[p], wzz));
            s0[p] = fma2_(hww, t0 & ABSM, s0[p]);
            u64 t1 = fma2_(wxx, dp1[p], fma2_(wyy, cp1[p], wzz));
            s1[p] = fma2_(hww, t1 & ABSM, s1[p]);
        }
    }

    // ---- Phase 3: softmax per row ----
    float sc0[8], sc1[8];
    #pragma unroll
    for (int p = 0; p < 4; p++) {
        upk(s0[p], sc0[2 * p], sc0[2 * p + 1]);
        upk(s1[p], sc1[2 * p], sc1[2 * p + 1]);
    }
    float mx0 = sc0[0], mx1 = sc1[0];
    #pragma unroll
    for (int i = 1; i < 8; i++) { mx0 = fmaxf(mx0, sc0[i]); mx1 = fmaxf(mx1, sc1[i]); }
    #pragma unroll
    for (int o = 16; o; o >>= 1) {
        mx0 = fmaxf(mx0, __shfl_xor_sync(0xffffffffu, mx0, o));
        mx1 = fmaxf(mx1, __shfl_xor_sync(0xffffffffu, mx1, o));
    }
    float sum0 = 0.f, sum1 = 0.f;
    #pragma unroll
    for (int i = 0; i < 8; i++) {
        sc0[i] = __expf(sc0[i] - mx0); sum0 += sc0[i];
        sc1[i] = __expf(sc1[i] - mx1); sum1 += sc1[i];
    }
    #pragma unroll
    for (int o = 16; o; o >>= 1) {
        sum0 += __shfl_xor_sync(0xffffffffu, sum0, o);
        sum1 += __shfl_xor_sync(0xffffffffu, sum1, o);
    }
    float inv0 = 1.f / sum0, inv1 = 1.f / sum1;

    // ---- Phase 4: AV accumulation (V pairs free via ulonglong2) ----
    u64 acc0[8], acc1[8];
    #pragma unroll
    for (int j = 0; j < 8; j++) { acc0[j] = 0ull; acc1[j] = 0ull; }
    #pragma unroll
    for (int i = 0; i < 8; i++) {
        int c = i * 32 + lane;
        u64 w0 = pk(sc0[i], sc0[i]);
        u64 w1 = pk(sc1[i], sc1[i]);
        #pragma unroll
        for (int j = 0; j < 4; j++) {
            ulonglong2 vv = *(const ulonglong2*)&Vs[c][j * 4];
            acc0[2 * j]     = fma2_(w0, vv.x, acc0[2 * j]);
            acc0[2 * j + 1] = fma2_(w0, vv.y, acc0[2 * j + 1]);
            acc1[2 * j]     = fma2_(w1, vv.x, acc1[2 * j]);
            acc1[2 * j + 1] = fma2_(w1, vv.y, acc1[2 * j + 1]);
        }
    }

    // ---- Phase 5: reduce-scatter epilogue ----
    int d0;
    float res0 = reduce16(acc0, lane, d0);
    int d1;
    float res1 = reduce16(acc1, lane, d1);
    if ((lane & 1) == 0) {
        out[(b * NQ + r0)     * (H_ * D_) + h * D_ + d0] = res0 * inv0;
        out[(b * NQ + r0 + 1) * (H_ * D_) + h * D_ + d1] = res1 * inv1;
    }
}

extern "C" void kernel_launch(void* const* d_in, const int* in_sizes, int n_in,
                              void* d_out, int out_size)
{
    const float* row_emb  = (const float*)d_in[0];
    const float* col_emb  = (const float*)d_in[1];
    const float* cost_mat = (const float*)d_in[2];
    const float* Wq       = (const float*)d_in[3];
    const float* Wk       = (const float*)d_in[4];
    const float* Wv       = (const float*)d_in[5];
    const float* m1w      = (const float*)d_in[6];
    const float* m1b      = (const float*)d_in[7];
    const float* m2w      = (const float*)d_in[8];
    // d_in[9] = mix2_bias: softmax-invariant, intentionally unused.
    float* out = (float*)d_out;

    dim3 gA(4, 32, 3);   // n-tiles x m-tiles x {Q,K,V} = 384 blocks
    qkv_kernel<<<gA, 128>>>(row_emb, col_emb, Wq, Wk, Wv);

    dim3 gB(16, 16, 4);  // 16-row tiles x heads x batch = 1024 blocks
    attn_kernel<<<gB, 256>>>(cost_mat, m1w, m1b, m2w, out);
}